// round 5
// baseline (speedup 1.0000x reference)
#include <cuda_runtime.h>
#include <math.h>

// iDDPMPrecond: (c_skip=1, c_out=-s, c_in=1/sqrt(s^2+1), c_noise=M-1-argmin_j|s-u_j|)
//
// Closed form: recurrence telescopes to 1+u[j]^2 = A/alpha_bar(j), A=alpha_bar(M),
// alpha_bar(j)=sin^2(c*j), c=pi/(2*M*(1+C2)). Exact inversion:
//   tan^2(c*j) = A/(s^2+1-A)  =>  jf = (pi/2 - atan(w))/c,  w = sqrt((s^2+1-A)/A)
// w in (0,1] for s in [0,1). Branch-free degree-9 minimax atan (err ~1e-4 rad
// = 0.14 index units). Exact argmin verified over the +/-1 window against the
// REAL u table (3 independent cached loads, strict < keeps first index on ties).

__global__ __launch_bounds__(256)
void precond_kernel(const float* __restrict__ sigma,
                    const float* __restrict__ u,
                    float* __restrict__ out,
                    int B, int M, int skip_count,
                    float oneMinusA, float invA, float half_pi_inv_c, float neg_inv_c)
{
    int tid = blockIdx.x * blockDim.x + threadIdx.x;

    // c_skip region (skip_count elements of 1.0f)
    if (tid < skip_count) out[tid] = 1.0f;
    if (tid >= B) return;

    float s  = sigma[tid];
    float s2p1 = fmaf(s, s, 1.0f);
    float ci = rsqrtf(s2p1);                 // c_in
    out[skip_count + tid]     = -s;          // c_out
    out[skip_count + B + tid] = ci;          // c_in

    // w = sqrt((s^2 + 1 - A) / A), in (0,1] for s in [0,1)
    float w  = sqrtf(fmaf(s, s, oneMinusA) * invA);
    float w2 = w * w;
    // atan(w) deg-9 odd minimax on [0,1]
    float p = fmaf(w2, 0.0208351f, -0.0851330f);
    p = fmaf(w2, p,  0.1801410f);
    p = fmaf(w2, p, -0.3302995f);
    p = fmaf(w2, p,  0.9998660f);
    float at = w * p;
    // jf = pi/(2c) - atan(w)/c
    float jf = fmaf(at, neg_inv_c, half_pi_inv_c);

    int jc = __float2int_rn(jf);
    jc = max(1, min(M - 1, jc));

    // Exact argmin over [jc-1, jc+1]; 3 independent cached loads.
    float d0 = fabsf(s - __ldg(&u[jc - 1]));
    float d1 = fabsf(s - __ldg(&u[jc]));
    float d2 = fabsf(s - __ldg(&u[jc + 1]));

    int   best_j = jc - 1;
    float best_d = d0;
    if (d1 < best_d) { best_d = d1; best_j = jc; }
    if (d2 < best_d) {              best_j = jc + 1; }

    out[skip_count + 2 * B + tid] = (float)(M - 1 - best_j);  // c_noise
}

extern "C" void kernel_launch(void* const* d_in, const int* in_sizes, int n_in,
                              void* d_out, int out_size)
{
    // inputs per metadata order: x (unused), sigma, u, M
    const float* sigma = (const float*)d_in[1];
    const float* u     = (const float*)d_in[2];
    const int B  = in_sizes[1];
    const int nU = in_sizes[2];
    const int M  = nU - 1;

    // Flattened tuple layout: [c_skip (skip elems)] [c_out B] [c_in B] [c_noise B]
    int skip = out_size - 3 * B;
    if (skip < 0) skip = 0;

    const double PI = 3.14159265358979323846;
    const double C2 = 0.008;
    const double c  = PI * 0.5 / ((double)M * (1.0 + C2));
    const double sM = sin(c * (double)M);
    const double A  = sM * sM;                       // alpha_bar(M)

    const float oneMinusA     = (float)(1.0 - A);
    const float invA          = (float)(1.0 / A);
    const float half_pi_inv_c = (float)(PI * 0.5 / c);
    const float neg_inv_c     = (float)(-1.0 / c);

    const int threads = 256;
    const int blocks  = (B + threads - 1) / threads;
    precond_kernel<<<blocks, threads>>>(sigma, u, (float*)d_out, B, M, skip,
                                        oneMinusA, invA, half_pi_inv_c, neg_inv_c);
}

// round 6
// speedup vs baseline: 1.0242x; 1.0242x over previous
#include <cuda_runtime.h>
#include <math.h>

// iDDPMPrecond: (c_skip=1, c_out=-s, c_in=1/sqrt(s^2+1), c_noise=M-1-argmin_j|s-u_j|)
//
// Closed form: recurrence telescopes to 1+u[j]^2 = A/alpha_bar(j), A=alpha_bar(M),
// alpha_bar(j)=sin^2(c*j), c=pi/(2*M*(1+C2)). Invert analytically:
//   j_real = asin(sqrtA * rsqrt(1+s^2)) / c   (reuses c_in); index error ~0.005.
// Exact argmin verified over the +/-1 window against the REAL u table
// (3 independent cached loads; strict < keeps first index on ties).
// Output region pointers pre-offset on the host (no per-thread address chains).

__global__ __launch_bounds__(256)
void precond_kernel(const float* __restrict__ sigma,
                    const float* __restrict__ u,
                    float* __restrict__ out_base,      // c_skip region
                    float* __restrict__ o_out,         // c_out
                    float* __restrict__ o_in,          // c_in
                    float* __restrict__ o_noise,       // c_noise
                    int B, int M, int skip_count,
                    float sqrtA, float inv_c)
{
    int tid = blockIdx.x * blockDim.x + threadIdx.x;

    if (tid < skip_count) out_base[tid] = 1.0f;
    if (tid >= B) return;

    float s  = sigma[tid];
    float ci = rsqrtf(fmaf(s, s, 1.0f));     // c_in

    // Analytic candidate index first so probe loads issue ASAP.
    float jf = asinf(sqrtA * ci) * inv_c;
    int jc = __float2int_rn(jf);
    jc = max(1, min(M - 1, jc));

    float u0 = __ldg(&u[jc - 1]);
    float u1 = __ldg(&u[jc]);
    float u2 = __ldg(&u[jc + 1]);

    o_out[tid] = -s;
    o_in[tid]  = ci;

    float d0 = fabsf(s - u0);
    float d1 = fabsf(s - u1);
    float d2 = fabsf(s - u2);

    int   best_j = jc - 1;
    float best_d = d0;
    if (d1 < best_d) { best_d = d1; best_j = jc; }
    if (d2 < best_d) {              best_j = jc + 1; }

    o_noise[tid] = (float)(M - 1 - best_j);
}

extern "C" void kernel_launch(void* const* d_in, const int* in_sizes, int n_in,
                              void* d_out, int out_size)
{
    // inputs per metadata order: x (unused), sigma, u, M
    const float* sigma = (const float*)d_in[1];
    const float* u     = (const float*)d_in[2];
    const int B  = in_sizes[1];
    const int nU = in_sizes[2];
    const int M  = nU - 1;

    // Flattened tuple layout: [c_skip (skip elems)] [c_out B] [c_in B] [c_noise B]
    int skip = out_size - 3 * B;
    if (skip < 0) skip = 0;

    float* ob = (float*)d_out;

    const double PI = 3.14159265358979323846;
    const double C2 = 0.008;
    const double c  = PI * 0.5 / ((double)M * (1.0 + C2));
    const float  sqrtA = (float)sin(c * (double)M);   // sqrt(alpha_bar(M))
    const float  inv_c = (float)(1.0 / c);

    const int threads = 256;
    const int blocks  = (B + threads - 1) / threads;
    precond_kernel<<<blocks, threads>>>(sigma, u,
                                        ob,                 // c_skip
                                        ob + skip,          // c_out
                                        ob + skip + B,      // c_in
                                        ob + skip + 2 * B,  // c_noise
                                        B, M, skip, sqrtA, inv_c);
}